// round 2
// baseline (speedup 1.0000x reference)
#include <cuda_runtime.h>
#include <math.h>
#include <stdint.h>

#define NN 128
#define DD 2048
#define EPSF 1e-12f
#define MARGINF 0.3f
#define NKC 64          // split-K chunks
#define KCHUNK 32       // K per chunk (64*32 = 2048)
#define SPAD 68         // smem row stride (floats): 16B-aligned, low-conflict

// ---------------- device scratch (no allocations allowed) ----------------
__device__ float g_part[NKC][NN * NN];   // split-K partial dot products (4 MB)
__device__ float g_norm[2 * NN];         // row norms: [0,128)=f1, [128,256)=f2
__device__ float g_dist_ap[NN];
__device__ int   g_sel1[NN];
__device__ int   g_sel2[NN];
__device__ float g_trip[NN];
__device__ int   g_done;

// ---------------- Kernel 1: split-K GEMM (f1 @ f2^T partials) + norms ----
// grid (2,2,NKC+1), block 256.
//   z < NKC : compute 64x64 tile (x=i-tile, y=j-tile) over K-chunk z
//   z == NKC: 4 blocks compute row norms of [f1;f2] (64 rows each) + reset g_done
__global__ void __launch_bounds__(256) k_gemm(const float* __restrict__ f1,
                                              const float* __restrict__ f2) {
    const int kc = blockIdx.z;
    const int tid = threadIdx.x;

    if (kc == NKC) {
        // ---- norms branch: 4 blocks x 8 warps x 8 rows = 256 rows ----
        const int id = blockIdx.y * 2 + blockIdx.x;   // 0..3
        const int w = tid >> 5, lane = tid & 31;      // 8 warps
        #pragma unroll
        for (int rr = 0; rr < 8; rr++) {
            const int row = id * 64 + w * 8 + rr;     // 0..255
            const float4* p4 = (const float4*)((row < NN) ? (f1 + row * DD)
                                                          : (f2 + (row - NN) * DD));
            float s = 0.f;
            #pragma unroll 4
            for (int t = lane; t < DD / 4; t += 32) {
                float4 v = p4[t];
                s += v.x * v.x + v.y * v.y + v.z * v.z + v.w * v.w;
            }
            #pragma unroll
            for (int o = 16; o; o >>= 1) s += __shfl_xor_sync(0xffffffffu, s, o);
            if (lane == 0) g_norm[row] = s;
        }
        if (id == 0 && tid == 0) g_done = 0;
        return;
    }

    // ---- GEMM branch: 64x64 tile, K-major transposed smem ----
    __shared__ float As[KCHUNK][SPAD];   // As[k][i]
    __shared__ float Bs[KCHUNK][SPAD];   // Bs[k][j]

    const int i0 = blockIdx.x * 64;
    const int j0 = blockIdx.y * 64;
    const int k0 = kc * KCHUNK;

    // Load + transpose: 64 rows x 32 K-floats per matrix = 512 float4.
    // Each thread: 2 float4 per matrix, scattered as 4 scalar STS each.
    #pragma unroll
    for (int s = 0; s < 2; s++) {
        const int f = tid + 256 * s;       // 0..511
        const int row = f >> 3;            // 0..63
        const int k4 = f & 7;              // float4 index in K
        float4 va = *(const float4*)(f1 + (i0 + row) * DD + k0 + k4 * 4);
        As[k4 * 4 + 0][row] = va.x; As[k4 * 4 + 1][row] = va.y;
        As[k4 * 4 + 2][row] = va.z; As[k4 * 4 + 3][row] = va.w;
        float4 vb = *(const float4*)(f2 + (j0 + row) * DD + k0 + k4 * 4);
        Bs[k4 * 4 + 0][row] = vb.x; Bs[k4 * 4 + 1][row] = vb.y;
        Bs[k4 * 4 + 2][row] = vb.z; Bs[k4 * 4 + 3][row] = vb.w;
    }
    __syncthreads();

    const int tx = tid & 15;   // j group (16)
    const int ty = tid >> 4;   // i group (16)

    float acc[4][4] = {};
    #pragma unroll
    for (int k = 0; k < KCHUNK; k++) {
        float4 a = *(const float4*)&As[k][ty * 4];   // broadcast within warp
        float4 b = *(const float4*)&Bs[k][tx * 4];
        acc[0][0] += a.x * b.x; acc[0][1] += a.x * b.y; acc[0][2] += a.x * b.z; acc[0][3] += a.x * b.w;
        acc[1][0] += a.y * b.x; acc[1][1] += a.y * b.y; acc[1][2] += a.y * b.z; acc[1][3] += a.y * b.w;
        acc[2][0] += a.z * b.x; acc[2][1] += a.z * b.y; acc[2][2] += a.z * b.z; acc[2][3] += a.z * b.w;
        acc[3][0] += a.w * b.x; acc[3][1] += a.w * b.y; acc[3][2] += a.w * b.z; acc[3][3] += a.w * b.w;
    }

    float* dst = &g_part[kc][0];
    #pragma unroll
    for (int m = 0; m < 4; m++) {
        float4 v = make_float4(acc[m][0], acc[m][1], acc[m][2], acc[m][3]);
        *(float4*)&dst[(i0 + ty * 4 + m) * NN + j0 + tx * 4] = v;
    }
}

// ---------------- Kernel 2: distances + hard example selection -----------
// grid 128 (row i), block 128 (col j)
__global__ void k_distsel(const int* __restrict__ tgt) {
    const int i = blockIdx.x;
    const int j = threadIdx.x;

    __shared__ int   st[NN];
    __shared__ float s_ap[4];
    __shared__ unsigned long long s_k1[4], s_k2[4];

    st[j] = tgt[j];

    // reduce split-K partials with 4-way ILP (fixed order -> deterministic)
    float d0 = 0.f, d1 = 0.f, d2s = 0.f, d3 = 0.f;
    #pragma unroll
    for (int kc = 0; kc < NKC; kc += 4) {
        d0 += g_part[kc + 0][i * NN + j];
        d1 += g_part[kc + 1][i * NN + j];
        d2s += g_part[kc + 2][i * NN + j];
        d3 += g_part[kc + 3][i * NN + j];
    }
    float dot = (d0 + d1) + (d2s + d3);

    float d2 = g_norm[i] + g_norm[NN + j] - 2.f * dot;
    float d = sqrtf(fmaxf(d2, EPSF));

    __syncthreads();
    const int ti = st[i];
    const bool pos = (st[j] == ti);

    // rank of j among negatives (ascending column order)
    int rank = 0;
    #pragma unroll 8
    for (int q = 0; q < NN; q++)
        rank += (q < j && st[q] != ti) ? 1 : 0;

    float apv = pos ? d : -INFINITY;
    // key encodes (distance, column) lexicographically: min-key => argmin with
    // first-occurrence tie-break (d > 0 so float bits are order-preserving)
    unsigned long long key =
        ((unsigned long long)__float_as_uint(d) << 32) | (unsigned)j;
    unsigned long long k1 = (!pos && rank < 56) ? key : ~0ull;
    unsigned long long k2 = (!pos && rank >= 56 && rank < 112) ? key : ~0ull;

    #pragma unroll
    for (int o = 16; o; o >>= 1) {
        apv = fmaxf(apv, __shfl_xor_sync(0xffffffffu, apv, o));
        unsigned long long t1 = __shfl_xor_sync(0xffffffffu, k1, o);
        unsigned long long t2 = __shfl_xor_sync(0xffffffffu, k2, o);
        k1 = (t1 < k1) ? t1 : k1;
        k2 = (t2 < k2) ? t2 : k2;
    }
    const int w = j >> 5;
    if ((j & 31) == 0) { s_ap[w] = apv; s_k1[w] = k1; s_k2[w] = k2; }
    __syncthreads();
    if (j == 0) {
        float ap = s_ap[0];
        unsigned long long m1 = s_k1[0], m2 = s_k2[0];
        #pragma unroll
        for (int q = 1; q < 4; q++) {
            ap = fmaxf(ap, s_ap[q]);
            if (s_k1[q] < m1) m1 = s_k1[q];
            if (s_k2[q] < m2) m2 = s_k2[q];
        }
        g_dist_ap[i] = ap;
        g_sel1[i] = (int)(m1 & 0xffffffffull);
        g_sel2[i] = (int)(m2 & 0xffffffffull);
    }
}

// ---------------- Kernel 3: dist_an + triplets + finalize ----------------
// grid 128 (anchor k), block 256
__global__ void k_distan(const float* __restrict__ f1, float* __restrict__ out,
                         int out_size) {
    const int k = blockIdx.x;
    const int tid = threadIdx.x;

    // index shuffle: feat_rgb_mid / feat_ir_mid mapping, anchor is always f1[k]
    int m = (k < 32) ? k : (k < 64) ? (k + 32) : (k < 96) ? (k - 32) : k;
    const int a = g_sel1[m];
    const int b = g_sel2[m];

    const float4* xk = (const float4*)(f1 + k * DD);
    const float4* xa = (const float4*)(f1 + a * DD);
    const float4* xb = (const float4*)(f1 + b * DD);

    float aa = 0.f, bb = 0.f, ab = 0.f;
    #pragma unroll
    for (int t = tid; t < DD / 4; t += 256) {
        float4 vk = xk[t], va = xa[t], vb = xb[t];
        float4 fm;
        fm.x = 0.5f * (va.x + vb.x); fm.y = 0.5f * (va.y + vb.y);
        fm.z = 0.5f * (va.z + vb.z); fm.w = 0.5f * (va.w + vb.w);
        aa += vk.x * vk.x + vk.y * vk.y + vk.z * vk.z + vk.w * vk.w;
        bb += fm.x * fm.x + fm.y * fm.y + fm.z * fm.z + fm.w * fm.w;
        ab += vk.x * fm.x + vk.y * fm.y + vk.z * fm.z + vk.w * fm.w;
    }
    #pragma unroll
    for (int o = 16; o; o >>= 1) {
        aa += __shfl_xor_sync(0xffffffffu, aa, o);
        bb += __shfl_xor_sync(0xffffffffu, bb, o);
        ab += __shfl_xor_sync(0xffffffffu, ab, o);
    }
    __shared__ float red[8][3];
    const int w = tid >> 5;
    if ((tid & 31) == 0) { red[w][0] = aa; red[w][1] = bb; red[w][2] = ab; }
    __syncthreads();

    if (tid == 0) {
        float saa = 0.f, sbb = 0.f, sab = 0.f;
        #pragma unroll
        for (int q = 0; q < 8; q++) { saa += red[q][0]; sbb += red[q][1]; sab += red[q][2]; }
        float d2 = saa + sbb - 2.f * sab;
        float dan = sqrtf(fmaxf(d2, EPSF));
        g_trip[k] = g_dist_ap[k] - dan + MARGINF;

        __threadfence();
        int done = atomicAdd(&g_done, 1);
        if (done == NN - 1) {
            // deterministic serial finalize
            float s = 0.f; int c = 0;
            #pragma unroll 8
            for (int q = 0; q < NN; q++) {
                float t = g_trip[q];
                if (t > 0.f) { s += t; c++; }
            }
            out[0] = s * (1.0f / 128.0f);
            if (out_size > 1) out[1] = (float)c;
        }
    }
}

// ---------------- launch ----------------
extern "C" void kernel_launch(void* const* d_in, const int* in_sizes, int n_in,
                              void* d_out, int out_size) {
    const float* f1 = (const float*)d_in[0];
    const float* f2 = (const float*)d_in[1];
    const int*   tgt = (const int*)d_in[2];
    (void)in_sizes; (void)n_in;

    k_gemm<<<dim3(2, 2, NKC + 1), 256>>>(f1, f2);
    k_distsel<<<NN, NN>>>(tgt);
    k_distan<<<NN, 256>>>(f1, (float*)d_out, out_size);
}

// round 3
// speedup vs baseline: 1.0454x; 1.0454x over previous
#include <cuda_runtime.h>
#include <math.h>
#include <stdint.h>

#define NN 128
#define DD 2048
#define EPSF 1e-12f
#define MARGINF 0.3f
#define NKC 32          // split-K chunks
#define KCHUNK 64       // K per chunk (32*64 = 2048)
#define SPAD 68         // smem row stride (floats): 16B aligned (68*4=272=17*16)
#define NBLK 136        // 128 GEMM + 8 norm blocks (all co-resident, <=148 SMs)

// ---------------- device scratch (no allocations allowed) ----------------
// transposed partials: g_part[i][kc][j]  -> phase-B reads are sequential
__device__ float g_part[NN * NKC * NN];  // 2 MB
__device__ float g_norm[2 * NN];
__device__ float g_dist_ap[NN];
__device__ int   g_sel1[NN];
__device__ int   g_sel2[NN];
__device__ float g_trip[NN];
__device__ int   g_c0, g_c1, g_c2;       // phase barriers (zero-init, self-resetting)

// packed f32x2 FMA: acc.{lo,hi} += a.{lo,hi} * b.{lo,hi}
__device__ __forceinline__ void ffma2(unsigned long long& acc,
                                      unsigned long long a, unsigned long long b) {
    asm("fma.rn.f32x2 %0, %1, %2, %0;" : "+l"(acc) : "l"(a), "l"(b));
}
__device__ __forceinline__ float2 up2(unsigned long long v) {
    float2 r;
    asm("mov.b64 {%0, %1}, %2;" : "=f"(r.x), "=f"(r.y) : "l"(v));
    return r;
}

// grid-wide spin barrier: all NBLK blocks resident by construction
__device__ __forceinline__ void gbar(int* c) {
    __threadfence();
    __syncthreads();
    if (threadIdx.x == 0) {
        atomicAdd(c, 1);
        while (*(volatile int*)c != NBLK) __nanosleep(64);
    }
    __syncthreads();
    __threadfence();
}

__global__ void __launch_bounds__(256, 1)
k_fused(const float* __restrict__ f1, const float* __restrict__ f2,
        const int* __restrict__ tgt, float* __restrict__ out, int out_size) {
    const int tid = threadIdx.x;
    const int bid = blockIdx.x + blockIdx.y * 2 + blockIdx.z * 4;  // 0..135

    __shared__ float As[KCHUNK][SPAD];   // As[i][k], row-major
    __shared__ float Bs[KCHUNK][SPAD];   // Bs[j][k]
    __shared__ int   st[NN];
    __shared__ float s_ap[4];
    __shared__ unsigned long long s_k1[4], s_k2[4];
    __shared__ float red[8][3];

    // ================= Phase A: split-K GEMM (z<32) or norms (z>=32) =====
    if (blockIdx.z < NKC) {
        const int i0 = blockIdx.x * 64;
        const int j0 = blockIdx.y * 64;
        const int kc = blockIdx.z;
        const int k0 = kc * KCHUNK;

        // load 64x64 tile of each matrix, row-major, float4 coalesced
        #pragma unroll
        for (int s = 0; s < 4; s++) {
            const int f = tid + 256 * s;           // 0..1023
            const int row = f >> 4;                // 0..63
            const int k4 = f & 15;
            float4 va = *(const float4*)(f1 + (size_t)(i0 + row) * DD + k0 + k4 * 4);
            float4 vb = *(const float4*)(f2 + (size_t)(j0 + row) * DD + k0 + k4 * 4);
            *(float4*)&As[row][k4 * 4] = va;
            *(float4*)&Bs[row][k4 * 4] = vb;
        }
        __syncthreads();

        const int ty4 = (tid >> 4) << 2;   // i sub-tile
        const int tx4 = (tid & 15) << 2;   // j sub-tile

        unsigned long long acc[4][4][2];
        #pragma unroll
        for (int m = 0; m < 4; m++)
            #pragma unroll
            for (int n = 0; n < 4; n++) { acc[m][n][0] = 0ull; acc[m][n][1] = 0ull; }

        #pragma unroll 4
        for (int kk = 0; kk < KCHUNK; kk += 4) {
            ulonglong2 a[4], b[4];
            #pragma unroll
            for (int m = 0; m < 4; m++) a[m] = *(const ulonglong2*)&As[ty4 + m][kk];
            #pragma unroll
            for (int n = 0; n < 4; n++) b[n] = *(const ulonglong2*)&Bs[tx4 + n][kk];
            #pragma unroll
            for (int m = 0; m < 4; m++)
                #pragma unroll
                for (int n = 0; n < 4; n++) {
                    ffma2(acc[m][n][0], a[m].x, b[n].x);
                    ffma2(acc[m][n][1], a[m].y, b[n].y);
                }
        }

        #pragma unroll
        for (int m = 0; m < 4; m++) {
            float v[4];
            #pragma unroll
            for (int n = 0; n < 4; n++) {
                float2 p0 = up2(acc[m][n][0]);
                float2 p1 = up2(acc[m][n][1]);
                v[n] = (p0.x + p0.y) + (p1.x + p1.y);
            }
            float4 o = make_float4(v[0], v[1], v[2], v[3]);
            *(float4*)&g_part[((size_t)(i0 + ty4 + m) * NKC + kc) * NN + j0 + tx4] = o;
        }
    } else {
        // ---- norms: 8 blocks x 8 warps x 4 rows = 256 rows, MLP across rows
        const int id = (blockIdx.z - NKC) * 4 + blockIdx.y * 2 + blockIdx.x;  // 0..7
        const int w = tid >> 5, lane = tid & 31;
        const int r0 = id * 32 + w * 4;            // 4 consecutive rows per warp
        const float4* p[4];
        #pragma unroll
        for (int r = 0; r < 4; r++) {
            const int row = r0 + r;
            p[r] = (const float4*)((row < NN) ? (f1 + (size_t)row * DD)
                                              : (f2 + (size_t)(row - NN) * DD));
        }
        float s0 = 0.f, s1 = 0.f, s2 = 0.f, s3 = 0.f;
        #pragma unroll 4
        for (int t = lane; t < DD / 4; t += 32) {
            float4 v0 = p[0][t], v1 = p[1][t], v2 = p[2][t], v3 = p[3][t];
            s0 += v0.x * v0.x + v0.y * v0.y + v0.z * v0.z + v0.w * v0.w;
            s1 += v1.x * v1.x + v1.y * v1.y + v1.z * v1.z + v1.w * v1.w;
            s2 += v2.x * v2.x + v2.y * v2.y + v2.z * v2.z + v2.w * v2.w;
            s3 += v3.x * v3.x + v3.y * v3.y + v3.z * v3.z + v3.w * v3.w;
        }
        #pragma unroll
        for (int o = 16; o; o >>= 1) {
            s0 += __shfl_xor_sync(0xffffffffu, s0, o);
            s1 += __shfl_xor_sync(0xffffffffu, s1, o);
            s2 += __shfl_xor_sync(0xffffffffu, s2, o);
            s3 += __shfl_xor_sync(0xffffffffu, s3, o);
        }
        if (lane == 0) {
            g_norm[r0 + 0] = s0; g_norm[r0 + 1] = s1;
            g_norm[r0 + 2] = s2; g_norm[r0 + 3] = s3;
        }
    }

    gbar(&g_c0);

    // ================= Phase B: distances + hard-example selection ========
    if (bid < NN) {
        const int i = bid;
        float d;
        if (tid < NN) {
            st[tid] = tgt[tid];
            const int j = tid;
            // sequential 16KB stream per block: g_part[i][kc][j]
            const float* pp = g_part + (size_t)i * NKC * NN + j;
            float a0 = 0.f, a1 = 0.f, a2 = 0.f, a3 = 0.f;
            #pragma unroll
            for (int kc = 0; kc < NKC; kc += 4) {
                a0 += __ldcg(pp + (size_t)(kc + 0) * NN);
                a1 += __ldcg(pp + (size_t)(kc + 1) * NN);
                a2 += __ldcg(pp + (size_t)(kc + 2) * NN);
                a3 += __ldcg(pp + (size_t)(kc + 3) * NN);
            }
            float dot = (a0 + a1) + (a2 + a3);
            float d2 = __ldcg(&g_norm[i]) + __ldcg(&g_norm[NN + j]) - 2.f * dot;
            d = sqrtf(fmaxf(d2, EPSF));
        }
        __syncthreads();
        if (tid < NN) {
            const int j = tid;
            const int ti = st[i];
            const bool pos = (st[j] == ti);

            int rank = 0;
            #pragma unroll 8
            for (int q = 0; q < NN; q++)
                rank += (q < j && st[q] != ti) ? 1 : 0;

            float apv = pos ? d : -INFINITY;
            unsigned long long key =
                ((unsigned long long)__float_as_uint(d) << 32) | (unsigned)j;
            unsigned long long k1 = (!pos && rank < 56) ? key : ~0ull;
            unsigned long long k2 = (!pos && rank >= 56 && rank < 112) ? key : ~0ull;

            #pragma unroll
            for (int o = 16; o; o >>= 1) {
                apv = fmaxf(apv, __shfl_xor_sync(0xffffffffu, apv, o));
                unsigned long long t1 = __shfl_xor_sync(0xffffffffu, k1, o);
                unsigned long long t2 = __shfl_xor_sync(0xffffffffu, k2, o);
                k1 = (t1 < k1) ? t1 : k1;
                k2 = (t2 < k2) ? t2 : k2;
            }
            const int w = j >> 5;
            if ((j & 31) == 0) { s_ap[w] = apv; s_k1[w] = k1; s_k2[w] = k2; }
        }
        __syncthreads();
        if (tid == 0) {
            float ap = s_ap[0];
            unsigned long long m1 = s_k1[0], m2 = s_k2[0];
            #pragma unroll
            for (int q = 1; q < 4; q++) {
                ap = fmaxf(ap, s_ap[q]);
                if (s_k1[q] < m1) m1 = s_k1[q];
                if (s_k2[q] < m2) m2 = s_k2[q];
            }
            g_dist_ap[i] = ap;
            g_sel1[i] = (int)(m1 & 0xffffffffull);
            g_sel2[i] = (int)(m2 & 0xffffffffull);
        }
    }

    gbar(&g_c1);

    // ================= Phase C: dist_an + triplet ==========================
    if (bid < NN) {
        const int k = bid;
        // feat_rgb_mid / feat_ir_mid index shuffle; anchor is always f1[k]
        int m = (k < 32) ? k : (k < 64) ? (k + 32) : (k < 96) ? (k - 32) : k;
        const int a = __ldcg(&g_sel1[m]);
        const int b = __ldcg(&g_sel2[m]);

        const float4* xk = (const float4*)(f1 + (size_t)k * DD);
        const float4* xa = (const float4*)(f1 + (size_t)a * DD);
        const float4* xb = (const float4*)(f1 + (size_t)b * DD);

        float aa = 0.f, bb = 0.f, ab = 0.f;
        #pragma unroll
        for (int t = tid; t < DD / 4; t += 256) {
            float4 vk = xk[t], va = xa[t], vb = xb[t];
            float4 fm;
            fm.x = 0.5f * (va.x + vb.x); fm.y = 0.5f * (va.y + vb.y);
            fm.z = 0.5f * (va.z + vb.z); fm.w = 0.5f * (va.w + vb.w);
            aa += vk.x * vk.x + vk.y * vk.y + vk.z * vk.z + vk.w * vk.w;
            bb += fm.x * fm.x + fm.y * fm.y + fm.z * fm.z + fm.w * fm.w;
            ab += vk.x * fm.x + vk.y * fm.y + vk.z * fm.z + vk.w * fm.w;
        }
        #pragma unroll
        for (int o = 16; o; o >>= 1) {
            aa += __shfl_xor_sync(0xffffffffu, aa, o);
            bb += __shfl_xor_sync(0xffffffffu, bb, o);
            ab += __shfl_xor_sync(0xffffffffu, ab, o);
        }
        const int w = tid >> 5;
        if ((tid & 31) == 0) { red[w][0] = aa; red[w][1] = bb; red[w][2] = ab; }
        __syncthreads();
        if (tid == 0) {
            float saa = 0.f, sbb = 0.f, sab = 0.f;
            #pragma unroll
            for (int q = 0; q < 8; q++) {
                saa += red[q][0]; sbb += red[q][1]; sab += red[q][2];
            }
            float d2 = saa + sbb - 2.f * sab;
            float dan = sqrtf(fmaxf(d2, EPSF));
            g_trip[k] = __ldcg(&g_dist_ap[k]) - dan + MARGINF;
        }
    }

    // ================= finalize: last-arriving block =======================
    __threadfence();
    __syncthreads();
    if (tid == 0) {
        int done = atomicAdd(&g_c2, 1);
        if (done == NBLK - 1) {
            float s = 0.f; int c = 0;
            #pragma unroll 8
            for (int q = 0; q < NN; q++) {
                float t = __ldcg(&g_trip[q]);
                if (t > 0.f) { s += t; c++; }
            }
            out[0] = s * (1.0f / 128.0f);
            if (out_size > 1) out[1] = (float)c;
            // reset barriers for next (graph-replay) launch
            g_c0 = 0; g_c1 = 0; g_c2 = 0;
        }
    }
}

// ---------------- launch ----------------
extern "C" void kernel_launch(void* const* d_in, const int* in_sizes, int n_in,
                              void* d_out, int out_size) {
    const float* f1 = (const float*)d_in[0];
    const float* f2 = (const float*)d_in[1];
    const int*   tgt = (const int*)d_in[2];
    (void)in_sizes; (void)n_in;

    k_fused<<<dim3(2, 2, NKC + 2), 256>>>(f1, f2, tgt, (float*)d_out, out_size);
}

// round 4
// speedup vs baseline: 1.1603x; 1.1099x over previous
#include <cuda_runtime.h>
#include <math.h>
#include <stdint.h>

#define NN 128
#define DD 2048
#define EPSF 1e-12f
#define MARGINF 0.3f
#define KC 32            // K per GEMM block
#define KP 16            // k-pairs per chunk
#define NKCH 64          // number of K chunks (64*32 = 2048)
#define NBLK 288         // 256 GEMM + 32 norm blocks; 2 blocks/SM -> all resident
#define S2 66            // smem row stride in float2 (528B: 16B-aligned)

// ---------------- device scratch (no allocations allowed) ----------------
// partials: g_part[i][kc][j] -> phase-B reads are sequential streams per i
__device__ float g_part[NN * NKCH * NN];   // 4 MB
__device__ float g_norm[2 * NN];
__device__ float g_dist_ap[NN];
__device__ int   g_sel1[NN];
__device__ int   g_sel2[NN];
__device__ float g_trip[NN];
__device__ int   g_c0, g_c1, g_c2;         // phase barriers (zero-init, self-reset)

// packed f32x2 FMA: acc.{lo,hi} += a.{lo,hi} * b.{lo,hi}
__device__ __forceinline__ void ffma2(unsigned long long& acc,
                                      unsigned long long a, unsigned long long b) {
    asm("fma.rn.f32x2 %0, %1, %2, %0;" : "+l"(acc) : "l"(a), "l"(b));
}
__device__ __forceinline__ float2 up2(unsigned long long v) {
    float2 r;
    asm("mov.b64 {%0, %1}, %2;" : "=f"(r.x), "=f"(r.y) : "l"(v));
    return r;
}

// grid-wide spin barrier: all NBLK blocks resident by construction
__device__ __forceinline__ void gbar(int* c) {
    __threadfence();
    __syncthreads();
    if (threadIdx.x == 0) {
        atomicAdd(c, 1);
        while (*(volatile int*)c != NBLK) __nanosleep(64);
    }
    __syncthreads();
    __threadfence();
}

__global__ void __launch_bounds__(256, 2)
k_fused(const float* __restrict__ f1, const float* __restrict__ f2,
        const int* __restrict__ tgt, float* __restrict__ out, int out_size) {
    const int tid = threadIdx.x;
    const int bid = blockIdx.x;

    __shared__ float2 As2[KP][S2];   // As2[kp][row] = (A[2kp][row], A[2kp+1][row])
    __shared__ float2 Bs2[KP][S2];
    __shared__ int    st[NN];
    __shared__ float  s_dot[NN];
    __shared__ float  s_ap[4];
    __shared__ unsigned long long s_k1[4], s_k2[4];
    __shared__ float  red[8][3];

    // ================= Phase A: split-K GEMM or norms ======================
    if (bid < 256) {
        const int kc = bid & 63;
        const int quad = bid >> 6;            // 0..3
        const int i0 = (quad & 1) * 64;
        const int j0 = (quad >> 1) * 64;
        const int k0 = kc * KC;

        // load 64x32 chunk of each matrix; store k-pair interleaved
        #pragma unroll
        for (int s = 0; s < 2; s++) {
            const int f = tid + 256 * s;      // 0..511
            const int row = f >> 3;           // 0..63
            const int k4 = f & 7;             // float4 index within 32-wide K
            float4 va = *(const float4*)(f1 + (size_t)(i0 + row) * DD + k0 + k4 * 4);
            float4 vb = *(const float4*)(f2 + (size_t)(j0 + row) * DD + k0 + k4 * 4);
            As2[2 * k4 + 0][row] = make_float2(va.x, va.y);
            As2[2 * k4 + 1][row] = make_float2(va.z, va.w);
            Bs2[2 * k4 + 0][row] = make_float2(vb.x, vb.y);
            Bs2[2 * k4 + 1][row] = make_float2(vb.z, vb.w);
        }
        __syncthreads();

        const int ty4 = (tid >> 4) << 2;      // i sub-tile (4 rows)
        const int tx4 = (tid & 15) << 2;      // j sub-tile (4 cols)

        unsigned long long acc[4][4];
        #pragma unroll
        for (int m = 0; m < 4; m++)
            #pragma unroll
            for (int n = 0; n < 4; n++) acc[m][n] = 0ull;

        // register double-buffered k-pair loop
        ulonglong2 a0 = *(const ulonglong2*)&As2[0][ty4];
        ulonglong2 a1 = *(const ulonglong2*)&As2[0][ty4 + 2];
        ulonglong2 b0 = *(const ulonglong2*)&Bs2[0][tx4];
        ulonglong2 b1 = *(const ulonglong2*)&Bs2[0][tx4 + 2];

        #pragma unroll
        for (int kp = 0; kp < KP; kp++) {
            ulonglong2 na0, na1, nb0, nb1;
            if (kp < KP - 1) {
                na0 = *(const ulonglong2*)&As2[kp + 1][ty4];
                na1 = *(const ulonglong2*)&As2[kp + 1][ty4 + 2];
                nb0 = *(const ulonglong2*)&Bs2[kp + 1][tx4];
                nb1 = *(const ulonglong2*)&Bs2[kp + 1][tx4 + 2];
            }
            unsigned long long A[4] = {a0.x, a0.y, a1.x, a1.y};
            unsigned long long B[4] = {b0.x, b0.y, b1.x, b1.y};
            #pragma unroll
            for (int m = 0; m < 4; m++)
                #pragma unroll
                for (int n = 0; n < 4; n++)
                    ffma2(acc[m][n], A[m], B[n]);
            if (kp < KP - 1) { a0 = na0; a1 = na1; b0 = nb0; b1 = nb1; }
        }

        #pragma unroll
        for (int m = 0; m < 4; m++) {
            float v[4];
            #pragma unroll
            for (int n = 0; n < 4; n++) {
                float2 p = up2(acc[m][n]);
                v[n] = p.x + p.y;
            }
            float4 o = make_float4(v[0], v[1], v[2], v[3]);
            *(float4*)&g_part[((size_t)(i0 + ty4 + m) * NKCH + kc) * NN + j0 + tx4] = o;
        }
    } else {
        // ---- norms: 32 blocks x 8 warps, one row per warp (256 rows) ----
        const int w = tid >> 5, lane = tid & 31;
        const int row = (bid - 256) * 8 + w;   // 0..255
        const float4* p = (const float4*)((row < NN) ? (f1 + (size_t)row * DD)
                                                     : (f2 + (size_t)(row - NN) * DD));
        float s = 0.f;
        #pragma unroll
        for (int t = lane; t < DD / 4; t += 32) {
            float4 v = p[t];
            s += v.x * v.x + v.y * v.y + v.z * v.z + v.w * v.w;
        }
        #pragma unroll
        for (int o = 16; o; o >>= 1) s += __shfl_xor_sync(0xffffffffu, s, o);
        if (lane == 0) g_norm[row] = s;
    }

    gbar(&g_c0);

    // ================= Phase B: distances + hard-example selection ========
    if (bid < NN) {
        const int i = bid;
        const int j = tid & 127;
        const int kh = tid >> 7;               // two K-halves over threads

        if (kh == 0) st[j] = tgt[j];

        // each half-thread sums 32 chunks: sequential 512B-stride stream
        const float* pp = g_part + ((size_t)i * NKCH + kh * 32) * NN + j;
        float a0 = 0.f, a1 = 0.f, a2 = 0.f, a3 = 0.f;
        #pragma unroll
        for (int kc = 0; kc < 32; kc += 4) {
            a0 += __ldcg(pp + (size_t)(kc + 0) * NN);
            a1 += __ldcg(pp + (size_t)(kc + 1) * NN);
            a2 += __ldcg(pp + (size_t)(kc + 2) * NN);
            a3 += __ldcg(pp + (size_t)(kc + 3) * NN);
        }
        float half_dot = (a0 + a1) + (a2 + a3);
        if (kh == 1) s_dot[j] = half_dot;
        __syncthreads();

        if (kh == 0) {
            float dot = half_dot + s_dot[j];
            float d2 = __ldcg(&g_norm[i]) + __ldcg(&g_norm[NN + j]) - 2.f * dot;
            float d = sqrtf(fmaxf(d2, EPSF));

            const int ti = st[i];
            const bool pos = (st[j] == ti);

            // rank of j among negatives (ascending column order)
            int rank = 0;
            #pragma unroll 8
            for (int q = 0; q < NN; q++)
                rank += (q < j && st[q] != ti) ? 1 : 0;

            float apv = pos ? d : -INFINITY;
            // (distance, column) lexicographic key: min-key == argmin with
            // first-occurrence tie-break (d > 0 so float bits order-preserve)
            unsigned long long key =
                ((unsigned long long)__float_as_uint(d) << 32) | (unsigned)j;
            unsigned long long k1 = (!pos && rank < 56) ? key : ~0ull;
            unsigned long long k2 = (!pos && rank >= 56 && rank < 112) ? key : ~0ull;

            #pragma unroll
            for (int o = 16; o; o >>= 1) {
                apv = fmaxf(apv, __shfl_xor_sync(0xffffffffu, apv, o));
                unsigned long long t1 = __shfl_xor_sync(0xffffffffu, k1, o);
                unsigned long long t2 = __shfl_xor_sync(0xffffffffu, k2, o);
                k1 = (t1 < k1) ? t1 : k1;
                k2 = (t2 < k2) ? t2 : k2;
            }
            const int w = j >> 5;
            if ((j & 31) == 0) { s_ap[w] = apv; s_k1[w] = k1; s_k2[w] = k2; }
        }
        __syncthreads();
        if (tid == 0) {
            float ap = s_ap[0];
            unsigned long long m1 = s_k1[0], m2 = s_k2[0];
            #pragma unroll
            for (int q = 1; q < 4; q++) {
                ap = fmaxf(ap, s_ap[q]);
                if (s_k1[q] < m1) m1 = s_k1[q];
                if (s_k2[q] < m2) m2 = s_k2[q];
            }
            g_dist_ap[i] = ap;
            g_sel1[i] = (int)(m1 & 0xffffffffull);
            g_sel2[i] = (int)(m2 & 0xffffffffull);
        }
    }

    gbar(&g_c1);

    // ================= Phase C: dist_an + triplet ==========================
    if (bid < NN) {
        const int k = bid;
        // feat_rgb_mid / feat_ir_mid index shuffle; anchor is always f1[k]
        int m = (k < 32) ? k : (k < 64) ? (k + 32) : (k < 96) ? (k - 32) : k;
        const int a = __ldcg(&g_sel1[m]);
        const int b = __ldcg(&g_sel2[m]);

        const float4* xk = (const float4*)(f1 + (size_t)k * DD);
        const float4* xa = (const float4*)(f1 + (size_t)a * DD);
        const float4* xb = (const float4*)(f1 + (size_t)b * DD);

        float aa = 0.f, bb = 0.f, ab = 0.f;
        #pragma unroll
        for (int t = tid; t < DD / 4; t += 256) {
            float4 vk = xk[t], va = xa[t], vb = xb[t];
            float4 fm;
            fm.x = 0.5f * (va.x + vb.x); fm.y = 0.5f * (va.y + vb.y);
            fm.z = 0.5f * (va.z + vb.z); fm.w = 0.5f * (va.w + vb.w);
            aa += vk.x * vk.x + vk.y * vk.y + vk.z * vk.z + vk.w * vk.w;
            bb += fm.x * fm.x + fm.y * fm.y + fm.z * fm.z + fm.w * fm.w;
            ab += vk.x * fm.x + vk.y * fm.y + vk.z * fm.z + vk.w * fm.w;
        }
        #pragma unroll
        for (int o = 16; o; o >>= 1) {
            aa += __shfl_xor_sync(0xffffffffu, aa, o);
            bb += __shfl_xor_sync(0xffffffffu, bb, o);
            ab += __shfl_xor_sync(0xffffffffu, ab, o);
        }
        const int w = tid >> 5;
        if ((tid & 31) == 0) { red[w][0] = aa; red[w][1] = bb; red[w][2] = ab; }
        __syncthreads();
        if (tid == 0) {
            float saa = 0.f, sbb = 0.f, sab = 0.f;
            #pragma unroll
            for (int q = 0; q < 8; q++) {
                saa += red[q][0]; sbb += red[q][1]; sab += red[q][2];
            }
            float d2 = saa + sbb - 2.f * sab;
            float dan = sqrtf(fmaxf(d2, EPSF));
            g_trip[k] = __ldcg(&g_dist_ap[k]) - dan + MARGINF;
        }
    }

    // ================= finalize: last-arriving block =======================
    __threadfence();
    __syncthreads();
    if (tid == 0) {
        int done = atomicAdd(&g_c2, 1);
        if (done == NBLK - 1) {
            float s = 0.f; int c = 0;
            #pragma unroll 8
            for (int q = 0; q < NN; q++) {
                float t = __ldcg(&g_trip[q]);
                if (t > 0.f) { s += t; c++; }
            }
            out[0] = s * (1.0f / 128.0f);
            if (out_size > 1) out[1] = (float)c;
            // reset barriers for next graph replay
            g_c0 = 0; g_c1 = 0; g_c2 = 0;
        }
    }
}

// ---------------- launch ----------------
extern "C" void kernel_launch(void* const* d_in, const int* in_sizes, int n_in,
                              void* d_out, int out_size) {
    const float* f1 = (const float*)d_in[0];
    const float* f2 = (const float*)d_in[1];
    const int*   tgt = (const int*)d_in[2];
    (void)in_sizes; (void)n_in;

    k_fused<<<NBLK, 256>>>(f1, f2, tgt, (float*)d_out, out_size);
}